// round 3
// baseline (speedup 1.0000x reference)
#include <cuda_runtime.h>
#include <cuda_bf16.h>
#include <math.h>

#define NPTS   8192
#define BATCH  4
#define K      16
#define TILE   2048
#define TPB    256
#define SPLIT  4
#define QPB    (TPB / SPLIT)      // 64 queries per block
#define NCELL  512                // 8x8x8 Morton cells

// ---------------- scratch (no allocs allowed) ----------------
__device__ float4 g_psort[BATCH * NPTS];   // sorted points: xyz + |p|^2
__device__ int    g_orig [BATCH * NPTS];   // sorted pos -> original index
__device__ int    g_cell [BATCH * NPTS];
__device__ int    g_rank [BATCH * NPTS];
__device__ int    g_hist [BATCH * NCELL];
__device__ int    g_off  [BATCH * NCELL];

__device__ __forceinline__ int morton3(int x, int y, int z) {
    int m = 0;
#pragma unroll
    for (int i = 0; i < 3; i++) {
        m |= (((x >> i) & 1) << (3 * i))
           | (((y >> i) & 1) << (3 * i + 1))
           | (((z >> i) & 1) << (3 * i + 2));
    }
    return m;
}

// ---------------- pass 0: zero histograms ----------------
__global__ void zero_hist_kernel() {
    g_hist[blockIdx.x * NCELL + threadIdx.x] = 0;
}

// ---------------- pass 1: cell id + rank within cell ----------------
__global__ void cell_kernel(const float* __restrict__ x) {
    const int gi = blockIdx.x * blockDim.x + threadIdx.x;   // 0..B*N-1
    const int b  = gi / NPTS;
    const float px = x[gi * 3 + 0];
    const float py = x[gi * 3 + 1];
    const float pz = x[gi * 3 + 2];
    const float s = 1.0f / 1.28f;   // 8 cells over [-5.12, 5.12]
    int ix = (int)((px + 5.12f) * s); ix = ix < 0 ? 0 : (ix > 7 ? 7 : ix);
    int iy = (int)((py + 5.12f) * s); iy = iy < 0 ? 0 : (iy > 7 ? 7 : iy);
    int iz = (int)((pz + 5.12f) * s); iz = iz < 0 ? 0 : (iz > 7 ? 7 : iz);
    const int cell = morton3(ix, iy, iz);
    const int r = atomicAdd(&g_hist[b * NCELL + cell], 1);
    g_cell[gi] = cell;
    g_rank[gi] = r;
}

// ---------------- pass 2: exclusive scan of 512 bins per batch ----------------
__global__ void scan_kernel() {
    __shared__ int s[NCELL];
    const int b = blockIdx.x, t = threadIdx.x;
    s[t] = g_hist[b * NCELL + t];
    __syncthreads();
    const int own = s[t];
    for (int off = 1; off < NCELL; off <<= 1) {
        int add = (t >= off) ? s[t - off] : 0;
        __syncthreads();
        s[t] += add;
        __syncthreads();
    }
    g_off[b * NCELL + t] = s[t] - own;   // exclusive
}

// ---------------- pass 3: scatter into Morton order ----------------
__global__ void scatter_kernel(const float* __restrict__ x) {
    const int gi = blockIdx.x * blockDim.x + threadIdx.x;
    const int b  = gi / NPTS;
    const int i  = gi - b * NPTS;
    const float px = x[gi * 3 + 0];
    const float py = x[gi * 3 + 1];
    const float pz = x[gi * 3 + 2];
    const int pos = g_off[b * NCELL + g_cell[gi]] + g_rank[gi];
    g_psort[b * NPTS + pos] = make_float4(px, py, pz, px * px + py * py + pz * pz);
    g_orig [b * NPTS + pos] = i;
}

// ---------------- main kernel ----------------
__global__ __launch_bounds__(TPB)
void eig_ratio_kernel(float* __restrict__ out) {
    __shared__ float4 sh_tile[TILE];    // 32 KB; reused as merge buffer

    const int b     = blockIdx.y;
    const int tid   = threadIdx.x;
    const int phase = tid & (SPLIT - 1);
    const int ql    = tid >> 2;                       // 0..63
    const int q     = blockIdx.x * QPB + ql;          // sorted-order query id
    const int bN    = b * NPTS;

    const float4 qp = g_psort[bN + q];
    const float qx = qp.x, qy = qp.y, qz = qp.z, qsq = qp.w;

    float bval[K];
    int   bidx[K];
#pragma unroll
    for (int t = 0; t < K; t++) { bval[t] = 3.4e38f; bidx[t] = 0; }
    float worst = 3.4e38f;

    for (int t0 = 0; t0 < NPTS; t0 += TILE) {
        __syncthreads();
        for (int i = tid; i < TILE; i += TPB)
            sh_tile[i] = g_psort[bN + t0 + i];
        __syncthreads();

#pragma unroll 4
        for (int j = phase; j < TILE; j += SPLIT) {
            const float4 c = sh_tile[j];
            const float dot = qx * c.x + qy * c.y + qz * c.z;
            const float d2  = fmaf(-2.0f, dot, qsq + c.w);
            if (d2 < worst) {
                int ms = 0; float mv = bval[0];
#pragma unroll
                for (int t = 1; t < K; t++)
                    if (bval[t] > mv) { mv = bval[t]; ms = t; }
#pragma unroll
                for (int t = 0; t < K; t++)
                    if (t == ms) { bval[t] = d2; bidx[t] = t0 + j; }
                worst = bval[0];
#pragma unroll
                for (int t = 1; t < K; t++) worst = fmaxf(worst, bval[t]);
            }
        }
    }

    // ---- merge 4 partial top-16 sets via smem ----
    __syncthreads();
    float2* mb = (float2*)sh_tile;      // 256*16*8B = 32KB
#pragma unroll
    for (int t = 0; t < K; t++)
        mb[tid * K + t] = make_float2(bval[t], __int_as_float(bidx[t]));
    __syncthreads();

    if (phase != 0) return;

#pragma unroll
    for (int pr = 1; pr < SPLIT; pr++) {
#pragma unroll
        for (int t = 0; t < K; t++) {
            const float2 e = mb[(tid + pr) * K + t];
            if (e.x < worst) {
                int ms = 0; float mv = bval[0];
#pragma unroll
                for (int u = 1; u < K; u++)
                    if (bval[u] > mv) { mv = bval[u]; ms = u; }
#pragma unroll
                for (int u = 0; u < K; u++)
                    if (u == ms) { bval[u] = e.x; bidx[u] = __float_as_int(e.y); }
                worst = bval[0];
#pragma unroll
                for (int u = 1; u < K; u++) worst = fmaxf(worst, bval[u]);
            }
        }
    }

    // ---- sort 16 ascending by d2 (static odd-even network) -> deterministic,
    //      matches reference top_k ordering ----
#pragma unroll
    for (int pass = 0; pass < K; pass++) {
#pragma unroll
        for (int t = (pass & 1); t + 1 < K; t += 2) {
            if (bval[t] > bval[t + 1]) {
                float tv = bval[t]; bval[t] = bval[t + 1]; bval[t + 1] = tv;
                int   ti = bidx[t]; bidx[t] = bidx[t + 1]; bidx[t + 1] = ti;
            }
        }
    }

    // ---- gather neighbors, covariance (fp32, same as reference) ----
    float nx[K], ny[K], nz[K];
#pragma unroll
    for (int t = 0; t < K; t++) {
        const float4 np = g_psort[bN + bidx[t]];
        nx[t] = np.x; ny[t] = np.y; nz[t] = np.z;
    }
    float mx = 0.f, my = 0.f, mz = 0.f;
#pragma unroll
    for (int t = 0; t < K; t++) { mx += nx[t]; my += ny[t]; mz += nz[t]; }
    const float invk = 1.0f / (float)K;
    mx *= invk; my *= invk; mz *= invk;

    float c00 = 0.f, c01 = 0.f, c02 = 0.f, c11 = 0.f, c12 = 0.f, c22 = 0.f;
#pragma unroll
    for (int t = 0; t < K; t++) {
        const float dx = nx[t] - mx, dy = ny[t] - my, dz = nz[t] - mz;
        c00 += dx * dx; c01 += dx * dy; c02 += dx * dz;
        c11 += dy * dy; c12 += dy * dz; c22 += dz * dz;
    }

    // ---- 3x3 symmetric eigenvalues, trigonometric closed form (fp64) ----
    const double a00 = (double)(c00 * invk);
    const double a01 = (double)(c01 * invk);
    const double a02 = (double)(c02 * invk);
    const double a11 = (double)(c11 * invk);
    const double a12 = (double)(c12 * invk);
    const double a22 = (double)(c22 * invk);

    const double qm = (a00 + a11 + a22) / 3.0;
    const double p1 = a01 * a01 + a02 * a02 + a12 * a12;
    const double d0 = a00 - qm, d1 = a11 - qm, d2e = a22 - qm;
    const double p2 = d0 * d0 + d1 * d1 + d2e * d2e + 2.0 * p1;

    double ratio;
    if (p2 <= 0.0) {
        ratio = 1.0;
    } else {
        const double pp  = sqrt(p2 / 6.0);
        const double inv = 1.0 / pp;
        const double b00 = d0 * inv, b11 = d1 * inv, b22 = d2e * inv;
        const double b01 = a01 * inv, b02 = a02 * inv, b12 = a12 * inv;
        const double detB = b00 * (b11 * b22 - b12 * b12)
                          - b01 * (b01 * b22 - b12 * b02)
                          + b02 * (b01 * b12 - b11 * b02);
        double r = 0.5 * detB;
        r = fmin(1.0, fmax(-1.0, r));
        const double phi = acos(r) / 3.0;
        const double e_big   = qm + 2.0 * pp * cos(phi);
        const double e_small = qm + 2.0 * pp * cos(phi + 2.0943951023931953);
        const double e_mid   = 3.0 * qm - e_big - e_small;
        ratio = e_big / e_mid;
    }

    out[bN + g_orig[bN + q]] = (float)ratio;
}

extern "C" void kernel_launch(void* const* d_in, const int* in_sizes, int n_in,
                              void* d_out, int out_size) {
    const float* x = (const float*)d_in[0];   // (4, 8192, 3) fp32
    float* out = (float*)d_out;               // (4, 8192) fp32

    zero_hist_kernel<<<BATCH, NCELL>>>();
    cell_kernel<<<(BATCH * NPTS) / 256, 256>>>(x);
    scan_kernel<<<BATCH, NCELL>>>();
    scatter_kernel<<<(BATCH * NPTS) / 256, 256>>>(x);

    dim3 grid(NPTS / QPB, BATCH);
    eig_ratio_kernel<<<grid, TPB>>>(out);
}